// round 2
// baseline (speedup 1.0000x reference)
#include <cuda_runtime.h>
#include <math.h>

// Problem constants
#define Bsz 16
#define CIn 32
#define COn 32
#define Hn  256
#define Wn  256
#define KM  32      // K0 = K1 = M = 32 (base and extra mode regions coincide)
#define SXn 64      // selected row-frequencies: 0..31 and 224..255
#define RTOT (Bsz*CIn*Hn)   // 131072 spatial rows for the W-direction DFT

// ---- scratch (allocation-free: __device__ globals) ----
__device__ float2 g_TW[Wn*KM];          // fwd col twiddle  [w][k]  = e^{-2pi i k w / 256}
__device__ float2 g_TH[SXn*Hn];         // fwd row twiddle  [sx][h] = e^{-2pi i kx h / 256}, kx = sx<32?sx:192+sx
__device__ float  g_Dc[KM*Wn];          // irfft basis cos  [k][w]  (alpha_k * cos / 256)
__device__ float  g_Ds[KM*Wn];          // irfft basis -sin [k][w]
__device__ float2 g_Xw[(size_t)RTOT*KM];         // after fwd-W: [b,ci,h][k]      33.5 MB
__device__ float2 g_Xf[(size_t)Bsz*CIn*SXn*KM];  // after fwd-H: [b,ci][sx][k]     8.4 MB
__device__ float2 g_Of[(size_t)Bsz*COn*SXn*KM];  // after mixing                   8.4 MB
__device__ float2 g_Tmp[(size_t)Bsz*COn*Hn*KM];  // after inv-H: [b,co,h][k]      33.5 MB

// ---- twiddle/basis init (recomputed every call; deterministic, ~free) ----
__global__ void k_init() {
    int t = blockIdx.x * blockDim.x + threadIdx.x;
    if (t < Wn*KM) {
        int w = t / KM, k = t % KM;
        float s, c;
        sincospif((float)(k * w) / 128.0f, &s, &c);   // theta = 2*pi*k*w/256
        g_TW[t] = make_float2(c, -s);
    }
    int t2 = t - Wn*KM;
    if (t2 >= 0 && t2 < SXn*Hn) {
        int sx = t2 / Hn, h = t2 % Hn;
        int kx = (sx < 32) ? sx : (192 + sx);         // 224..255 for sx 32..63
        float s, c;
        sincospif((float)(kx * h) / 128.0f, &s, &c);
        g_TH[t2] = make_float2(c, -s);
    }
    int t3 = t2 - SXn*Hn;
    if (t3 >= 0 && t3 < KM*Wn) {
        int k = t3 / Wn, w = t3 % Wn;
        float s, c;
        sincospif((float)(k * w) / 128.0f, &s, &c);
        float alpha = ((k == 0) ? 1.0f : 2.0f) * (1.0f / 256.0f);  // irfft fold + inverse ortho norm
        g_Dc[t3] =  alpha * c;
        g_Ds[t3] = -alpha * s;
    }
}

// ---- K1: forward DFT along W (real input -> 32 complex modes) ----
// C[r][k] = sum_w x[r][w] * e^{-2pi i k w/256};  r = (b,ci,h) flat (131072 rows)
__global__ void __launch_bounds__(256) k_fwdW(const float* __restrict__ x) {
    __shared__ float  As[64][33];
    __shared__ float2 Ts[32][32];
    int tx = threadIdx.x & 31, ty = threadIdx.x >> 5;
    size_t rowBase = (size_t)blockIdx.x * 64;
    float2 acc[8];
    #pragma unroll
    for (int i = 0; i < 8; i++) acc[i] = make_float2(0.f, 0.f);
    for (int wc = 0; wc < 8; wc++) {
        #pragma unroll
        for (int i = 0; i < 8; i++) {
            int r = ty + i * 8;
            As[r][tx] = x[(rowBase + r) * 256 + wc * 32 + tx];
        }
        #pragma unroll
        for (int i = 0; i < 4; i++) {
            int idx = threadIdx.x + i * 256;        // 0..1023: wl=idx>>5, k=idx&31
            Ts[idx >> 5][idx & 31] = g_TW[(wc * 32 + (idx >> 5)) * 32 + (idx & 31)];
        }
        __syncthreads();
        #pragma unroll
        for (int i = 0; i < 32; i++) {
            float2 tv = Ts[i][tx];
            #pragma unroll
            for (int r8 = 0; r8 < 8; r8++) {
                float a = As[ty * 8 + r8][i];       // warp-uniform -> broadcast
                acc[r8].x = fmaf(a, tv.x, acc[r8].x);
                acc[r8].y = fmaf(a, tv.y, acc[r8].y);
            }
        }
        __syncthreads();
    }
    #pragma unroll
    for (int r8 = 0; r8 < 8; r8++)
        g_Xw[(rowBase + ty * 8 + r8) * 32 + tx] = acc[r8];
}

// ---- K2: forward DFT along H restricted to 64 selected kx (complex x complex) ----
// Xf[bci][sx][k] = (1/256) * sum_h Xw[bci][h][k] * e^{-2pi i kx h/256}
__global__ void __launch_bounds__(256) k_fwdH() {
    __shared__ float2 Xs[32][32];
    __shared__ float2 Es[64][32];
    int tx = threadIdx.x & 31, ty = threadIdx.x >> 5;
    size_t bci = blockIdx.x;
    const float2* Xwp = g_Xw + bci * 256 * 32;
    float2 acc[8];
    #pragma unroll
    for (int j = 0; j < 8; j++) acc[j] = make_float2(0.f, 0.f);
    for (int hc = 0; hc < 8; hc++) {
        #pragma unroll
        for (int i = 0; i < 4; i++) {
            int idx = threadIdx.x + i * 256;        // hl=idx>>5, k=idx&31
            Xs[idx >> 5][idx & 31] = Xwp[(size_t)(hc * 32 + (idx >> 5)) * 32 + (idx & 31)];
        }
        #pragma unroll
        for (int i = 0; i < 8; i++) {
            int idx = threadIdx.x + i * 256;        // sx=idx>>5, hl=idx&31
            Es[idx >> 5][idx & 31] = g_TH[(idx >> 5) * 256 + hc * 32 + (idx & 31)];
        }
        __syncthreads();
        #pragma unroll
        for (int i = 0; i < 32; i++) {
            float2 xv = Xs[i][tx];
            #pragma unroll
            for (int j = 0; j < 8; j++) {
                float2 e = Es[ty * 8 + j][i];       // warp-uniform -> broadcast
                acc[j].x = fmaf(xv.x, e.x, fmaf(-xv.y, e.y, acc[j].x));
                acc[j].y = fmaf(xv.x, e.y, fmaf( xv.y, e.x, acc[j].y));
            }
        }
        __syncthreads();
    }
    const float norm = 1.0f / 256.0f;               // forward ortho normalization
    #pragma unroll
    for (int j = 0; j < 8; j++) {
        int sx = ty * 8 + j;
        g_Xf[(bci * 64 + sx) * 32 + tx] = make_float2(acc[j].x * norm, acc[j].y * norm);
    }
}

// ---- K3: channel mixing with per-batch hierarchical mode scaling ----
// out[b][co] = sum_ci Xf[b][ci] * (W[ci][co] + s(b,kx,ky) * We[ci][co])   (complex)
__global__ void __launch_bounds__(256) k_mix(const float* __restrict__ fs,
                                             const float* __restrict__ w0a,
                                             const float* __restrict__ w1a,
                                             const float* __restrict__ we0a,
                                             const float* __restrict__ we1a) {
    __shared__ float2 Ws[1024];
    __shared__ float2 Wes[1024];
    __shared__ float2 Xs[512];
    __shared__ float  ssm[16];
    int bi = blockIdx.x;
    int r  = bi >> 10;
    int kx = (bi >> 5) & 31;
    int ky = bi & 31;
    int kxy = kx * 32 + ky;
    int sxg = r * 32 + kx;
    const float2* wb  = (const float2*)(r ? w1a  : w0a);
    const float2* web = (const float2*)(r ? we1a : we0a);
    int tid = threadIdx.x;
    for (int p = tid; p < 1024; p += 256) {
        Ws[p]  = wb [(size_t)p * 1024 + kxy];       // (ci*32+co)*K0*K1 + kxy
        Wes[p] = web[(size_t)p * 1024 + kxy];
    }
    for (int p = tid; p < 512; p += 256)            // p = b*32 + ci
        Xs[p] = g_Xf[((size_t)p * 64 + sxg) * 32 + ky];
    if (tid < 16) {
        int idx;                                     // hierarchical quadrant index (LEVEL0=3, KAPPA=8)
        if (kx < 8 && ky < 8)        idx = 0;
        else if (kx < 16 && ky < 16) idx = (kx < 8) ? 1 : ((ky < 8) ? 2 : 3);
        else                         idx = (kx < 16) ? 4 : ((ky < 16) ? 5 : 6);
        ssm[tid] = fs[tid * 7 + idx];
    }
    __syncthreads();
    int co = tid & 31;
    int bh = tid >> 5;
    #pragma unroll
    for (int bb = 0; bb < 2; bb++) {
        int b = bh + bb * 8;
        float sb = ssm[b];
        float2 acc = make_float2(0.f, 0.f);
        #pragma unroll
        for (int ci = 0; ci < 32; ci++) {
            float2 xv = Xs[b * 32 + ci];            // warp-uniform -> broadcast
            float2 w0 = Ws [ci * 32 + co];
            float2 we = Wes[ci * 32 + co];
            float wr = fmaf(sb, we.x, w0.x);
            float wi = fmaf(sb, we.y, w0.y);
            acc.x = fmaf(xv.x, wr, fmaf(-xv.y, wi, acc.x));
            acc.y = fmaf(xv.x, wi, fmaf( xv.y, wr, acc.y));
        }
        g_Of[(((size_t)b * 32 + co) * 64 + sxg) * 32 + ky] = acc;
    }
}

// ---- K4: inverse DFT along H (64 modes -> 256 rows, complex) ----
// Tmp[bco][h][k] = sum_sx Of[bco][sx][k] * conj(E[sx][h])
__global__ void __launch_bounds__(256) k_invH() {
    __shared__ float2 Os[64][32];
    __shared__ float2 Es[64][32];
    int tx = threadIdx.x & 31, ty = threadIdx.x >> 5;
    size_t bco = blockIdx.x;
    const float2* Op = g_Of + bco * 64 * 32;
    #pragma unroll
    for (int i = 0; i < 8; i++) {
        int idx = threadIdx.x + i * 256;
        Os[idx >> 5][idx & 31] = Op[idx];
    }
    for (int hc = 0; hc < 8; hc++) {
        __syncthreads();                            // also covers initial Os fill
        #pragma unroll
        for (int i = 0; i < 8; i++) {
            int idx = threadIdx.x + i * 256;        // sx=idx>>5, hl=idx&31
            Es[idx >> 5][idx & 31] = g_TH[(idx >> 5) * 256 + hc * 32 + (idx & 31)];
        }
        __syncthreads();
        float2 acc[4];
        #pragma unroll
        for (int j = 0; j < 4; j++) acc[j] = make_float2(0.f, 0.f);
        #pragma unroll 8
        for (int sx = 0; sx < 64; sx++) {
            float2 w = Os[sx][tx];
            #pragma unroll
            for (int j = 0; j < 4; j++) {
                float2 e = Es[sx][ty * 4 + j];      // warp-uniform -> broadcast
                acc[j].x = fmaf(w.x, e.x, fmaf( w.y, e.y, acc[j].x));   // w * conj(e)
                acc[j].y = fmaf(w.y, e.x, fmaf(-w.x, e.y, acc[j].y));
            }
        }
        #pragma unroll
        for (int j = 0; j < 4; j++) {
            int h = hc * 32 + ty * 4 + j;
            g_Tmp[(bco * 256 + h) * 32 + tx] = acc[j];
        }
    }
}

// ---- K5: inverse real DFT along W (32 complex modes -> 256 real samples) ----
// out[r][w] = sum_k ( Tr[k]*Dc[k][w] + Ti[k]*Ds[k][w] )
__global__ void __launch_bounds__(256) k_irfftW(float* __restrict__ out) {
    __shared__ float2 Ts[32][33];
    int tid = threadIdx.x;                          // tid = w
    size_t rowBase = (size_t)blockIdx.x * 32;
    #pragma unroll
    for (int i = 0; i < 4; i++) {
        int idx = tid + i * 256;                    // r=idx>>5, k=idx&31
        Ts[idx >> 5][idx & 31] = g_Tmp[(rowBase + (idx >> 5)) * 32 + (idx & 31)];
    }
    __syncthreads();
    float acc[32];
    #pragma unroll
    for (int r = 0; r < 32; r++) acc[r] = 0.f;
    #pragma unroll 4
    for (int k = 0; k < 32; k++) {
        float dc = g_Dc[k * 256 + tid];
        float ds = g_Ds[k * 256 + tid];
        #pragma unroll
        for (int r = 0; r < 32; r++) {
            float2 t = Ts[r][k];                    // warp-uniform -> broadcast
            acc[r] = fmaf(t.x, dc, fmaf(t.y, ds, acc[r]));
        }
    }
    #pragma unroll
    for (int r = 0; r < 32; r++)
        out[(rowBase + r) * 256 + tid] = acc[r];
}

extern "C" void kernel_launch(void* const* d_in, const int* in_sizes, int n_in,
                              void* d_out, int out_size) {
    const float* x   = (const float*)d_in[0];
    const float* fs  = (const float*)d_in[1];
    const float* w0  = (const float*)d_in[2];
    const float* w1  = (const float*)d_in[3];
    const float* we0 = (const float*)d_in[4];
    const float* we1 = (const float*)d_in[5];
    float* out = (float*)d_out;

    k_init<<<128, 256>>>();
    k_fwdW<<<RTOT / 64, 256>>>(x);          // 2048 blocks
    k_fwdH<<<Bsz * CIn, 256>>>();           // 512 blocks
    k_mix<<<2 * KM * KM, 256>>>(fs, w0, w1, we0, we1);  // 2048 blocks
    k_invH<<<Bsz * COn, 256>>>();           // 512 blocks
    k_irfftW<<<RTOT / 32, 256>>>(out);      // 4096 blocks
}

// round 3
// speedup vs baseline: 1.3161x; 1.3161x over previous
#include <cuda_runtime.h>
#include <math.h>

// Problem constants
#define Bsz 16
#define CIn 32
#define COn 32
#define Hn  256
#define Wn  256
#define KM  32      // K0 = K1 = M = 32 (base and extra mode regions coincide)
#define SXn 64      // selected row-frequencies: 0..31 and 224..255
#define RTOT (Bsz*CIn*Hn)   // 131072 rows for the W-direction DFT

// ---- tables ----
__device__ float2 g_T32[32*32];   // [b][k]  e^{-2pi i k b/256}
__device__ float2 g_TV [64*32];   // [sx][v] e^{-2pi i kx(sx) v/256}
__device__ float2 g_TI [32*32];   // [k][v]  alpha_k * e^{+2pi i k v/256}  (alpha=(k?2:1)/256)
__device__ float2 g_E8 [8*8];     // [m][a]  e^{-2pi i m a/8}
__device__ float2 g_E8i[8*8];     // [m][a]  e^{+2pi i m a/8}

// ---- scratch ----
__device__ float2 g_Xw[(size_t)RTOT*KM];          // after fwd-W  [row][k]
__device__ float2 g_Xf[(size_t)Bsz*CIn*SXn*KM];   // after fwd-H  [b*32+ci][sx][k]
__device__ float2 g_Of[(size_t)Bsz*COn*SXn*KM];   // after mix    [b*32+co][sx][k]
__device__ float2 g_Tmp[(size_t)Bsz*COn*Hn*KM];   // after inv-H  [row][k]

__global__ void k_init() {
    int t = blockIdx.x * blockDim.x + threadIdx.x;
    if (t < 1024) {                                 // g_T32
        int b = t >> 5, k = t & 31;
        float s, c; sincospif((float)(k * b) / 128.0f, &s, &c);
        g_T32[t] = make_float2(c, -s);
    }
    int t1 = t - 1024;
    if (t1 >= 0 && t1 < 2048) {                     // g_TV
        int sx = t1 >> 5, v = t1 & 31;
        int kx = (sx < 32) ? sx : (192 + sx);
        float s, c; sincospif((float)(kx * v) / 128.0f, &s, &c);
        g_TV[t1] = make_float2(c, -s);
    }
    int t2 = t1 - 2048;
    if (t2 >= 0 && t2 < 1024) {                     // g_TI
        int k = t2 >> 5, v = t2 & 31;
        float s, c; sincospif((float)(k * v) / 128.0f, &s, &c);
        float alpha = ((k == 0) ? 1.0f : 2.0f) * (1.0f / 256.0f);
        g_TI[t2] = make_float2(alpha * c, alpha * s);
    }
    int t3 = t2 - 1024;
    if (t3 >= 0 && t3 < 64) {                       // g_E8 / g_E8i
        int m = t3 >> 3, a = t3 & 7;
        float s, c; sincospif((float)(m * a) / 4.0f, &s, &c);
        g_E8 [t3] = make_float2(c, -s);
        g_E8i[t3] = make_float2(c,  s);
    }
}

// ---- K1: fwd DFT along W, radix split w = b + 32a ----
__global__ void __launch_bounds__(256) k_fwdW(const float* __restrict__ x) {
    __shared__ float  Xs[16][256];
    __shared__ float2 Ys[16][32][5];      // [r][b][m], m=0..4 (Hermitian)
    __shared__ float2 T32s[32][32];       // [b][k]
    __shared__ float2 E8s[5][8];
    int t = threadIdx.x;
    size_t rowBase = (size_t)blockIdx.x * 16;
    const float4* xg = (const float4*)(x + rowBase * 256);
    float4* xs4 = (float4*)&Xs[0][0];
    #pragma unroll
    for (int i = 0; i < 4; i++) xs4[t + 256*i] = xg[t + 256*i];
    #pragma unroll
    for (int i = 0; i < 4; i++) ((float2*)T32s)[t + 256*i] = g_T32[t + 256*i];
    if (t < 40) ((float2*)E8s)[t] = g_E8[t];
    __syncthreads();
    // stage1: 8-pt real DFT per (r,b); 512 tasks, 2/thread
    #pragma unroll
    for (int it = 0; it < 2; it++) {
        int task = t + 256*it;
        int r = task >> 5, b = task & 31;
        float xa[8];
        #pragma unroll
        for (int a = 0; a < 8; a++) xa[a] = Xs[r][b + 32*a];
        #pragma unroll
        for (int m = 0; m < 5; m++) {
            float yr = 0.f, yi = 0.f;
            #pragma unroll
            for (int a = 0; a < 8; a++) {
                float2 e = E8s[m][a];
                yr = fmaf(xa[a], e.x, yr);
                yi = fmaf(xa[a], e.y, yi);
            }
            Ys[r][b][m] = make_float2(yr, yi);
        }
    }
    __syncthreads();
    // stage2: C[k] = sum_b T32[b][k] * Y[b][k&7]  (conj fold for m>4)
    int k = t & 31, r0 = t >> 5;
    int m0 = k & 7;
    int sel = (m0 > 4) ? (8 - m0) : m0;
    float sgn = (m0 > 4) ? -1.f : 1.f;
    #pragma unroll
    for (int rr = 0; rr < 2; rr++) {
        int r = r0 + 8*rr;
        float ax = 0.f, ay = 0.f;
        #pragma unroll 8
        for (int b = 0; b < 32; b++) {
            float2 y  = Ys[r][b][sel];
            float  yi = sgn * y.y;
            float2 tw = T32s[b][k];
            ax = fmaf(y.x, tw.x, fmaf(-yi, tw.y, ax));
            ay = fmaf(y.x, tw.y, fmaf( yi, tw.x, ay));
        }
        g_Xw[(rowBase + r) * 32 + k] = make_float2(ax, ay);
    }
}

// ---- K2: fwd DFT along H on 64 selected kx, radix split h = v + 32a ----
__global__ void __launch_bounds__(256) k_fwdH() {
    __shared__ float2 Xs[256][8];         // [h][k] for this k-quarter
    __shared__ float2 Ys[32][8][8];       // [v][m][k]
    __shared__ float2 E8s[8][8];
    int t = threadIdx.x;
    int bci = blockIdx.x >> 2, kq = blockIdx.x & 3;
    const float2* Xp = g_Xw + (size_t)bci * 256 * 32 + kq * 8;
    #pragma unroll
    for (int i = 0; i < 8; i++) {
        int idx = t + 256*i;
        Xs[idx >> 3][idx & 7] = Xp[(size_t)(idx >> 3) * 32 + (idx & 7)];
    }
    if (t < 64) ((float2*)E8s)[t] = g_E8[t];
    __syncthreads();
    // stage1: Y[v][m][k] = sum_a X[v+32a][k] * E8[m][a]
    int v = t >> 3, k = t & 7;
    {
        float2 xa[8];
        #pragma unroll
        for (int a = 0; a < 8; a++) xa[a] = Xs[v + 32*a][k];
        #pragma unroll
        for (int m = 0; m < 8; m++) {
            float yr = 0.f, yi = 0.f;
            #pragma unroll
            for (int a = 0; a < 8; a++) {
                float2 e = E8s[m][a];
                yr = fmaf(xa[a].x, e.x, fmaf(-xa[a].y, e.y, yr));
                yi = fmaf(xa[a].x, e.y, fmaf( xa[a].y, e.x, yi));
            }
            Ys[v][m][k] = make_float2(yr, yi);
        }
    }
    __syncthreads();
    // stage2: out[sx][k] = (1/256) sum_v TV[sx][v] * Y[v][sx&7][k]; sx2 and sx2+32 share m
    int k2 = t & 7, sx2 = t >> 3;
    int m = sx2 & 7;
    float a0x = 0.f, a0y = 0.f, a1x = 0.f, a1y = 0.f;
    #pragma unroll 8
    for (int vv = 0; vv < 32; vv++) {
        float2 y  = Ys[vv][m][k2];
        float2 t0 = g_TV[sx2 * 32 + vv];
        float2 t1 = g_TV[(sx2 + 32) * 32 + vv];
        a0x = fmaf(y.x, t0.x, fmaf(-y.y, t0.y, a0x));
        a0y = fmaf(y.x, t0.y, fmaf( y.y, t0.x, a0y));
        a1x = fmaf(y.x, t1.x, fmaf(-y.y, t1.y, a1x));
        a1y = fmaf(y.x, t1.y, fmaf( y.y, t1.x, a1y));
    }
    const float nrm = 1.0f / 256.0f;
    g_Xf[((size_t)bci * 64 + sx2)      * 32 + kq * 8 + k2] = make_float2(a0x * nrm, a0y * nrm);
    g_Xf[((size_t)bci * 64 + sx2 + 32) * 32 + kq * 8 + k2] = make_float2(a1x * nrm, a1y * nrm);
}

// ---- K3: channel mixing, coalesced weights, registers only ----
__global__ void __launch_bounds__(256) k_mix(const float* __restrict__ fs,
                                             const float* __restrict__ w0a,
                                             const float* __restrict__ w1a,
                                             const float* __restrict__ we0a,
                                             const float* __restrict__ we1a) {
    int bid = blockIdx.x;
    int bq = bid & 3, kx = (bid >> 2) & 31, r = bid >> 7;
    int t = threadIdx.x;
    int ky = t & 31, co0 = (t >> 5) * 4;
    int sxg = r * 32 + kx;
    const float2* wb  = (const float2*)(r ? w1a  : w0a);
    const float2* web = (const float2*)(r ? we1a : we0a);
    int kxy = kx * 32 + ky;
    int idx;                                         // hierarchical quadrant (LEVEL0=3, KAPPA=8)
    if (kx < 8 && ky < 8)        idx = 0;
    else if (kx < 16 && ky < 16) idx = (kx < 8) ? 1 : ((ky < 8) ? 2 : 3);
    else                         idx = (kx < 16) ? 4 : ((ky < 16) ? 5 : 6);
    float sb[4];
    #pragma unroll
    for (int j = 0; j < 4; j++) sb[j] = fs[(bq * 4 + j) * 7 + idx];
    float ax[4][4], ay[4][4];
    #pragma unroll
    for (int j = 0; j < 4; j++)
        #pragma unroll
        for (int b = 0; b < 4; b++) { ax[j][b] = 0.f; ay[j][b] = 0.f; }
    for (int ci = 0; ci < 32; ci++) {
        float2 xv[4];
        #pragma unroll
        for (int b = 0; b < 4; b++)
            xv[b] = g_Xf[(((size_t)(bq * 4 + b) * 32 + ci) * 64 + sxg) * 32 + ky];
        #pragma unroll
        for (int j = 0; j < 4; j++) {
            float2 w  = wb [((size_t)ci * 32 + co0 + j) * 1024 + kxy];
            float2 we = web[((size_t)ci * 32 + co0 + j) * 1024 + kxy];
            #pragma unroll
            for (int b = 0; b < 4; b++) {
                float wr = fmaf(sb[b], we.x, w.x);
                float wi = fmaf(sb[b], we.y, w.y);
                ax[j][b] = fmaf(xv[b].x, wr, fmaf(-xv[b].y, wi, ax[j][b]));
                ay[j][b] = fmaf(xv[b].x, wi, fmaf( xv[b].y, wr, ay[j][b]));
            }
        }
    }
    #pragma unroll
    for (int j = 0; j < 4; j++)
        #pragma unroll
        for (int b = 0; b < 4; b++)
            g_Of[(((size_t)(bq * 4 + b) * 32 + co0 + j) * 64 + sxg) * 32 + ky] =
                make_float2(ax[j][b], ay[j][b]);
}

// ---- K4: inverse DFT along H, radix split h = v + 32a, stages fused per-thread ----
__global__ void __launch_bounds__(256) k_invH() {
    __shared__ float2 Ofs[64][8];
    __shared__ float2 E8is[8][8];
    int t = threadIdx.x;
    int bco = blockIdx.x >> 2, kq = blockIdx.x & 3;
    const float2* Op = g_Of + (size_t)bco * 64 * 32 + kq * 8;
    #pragma unroll
    for (int i = 0; i < 2; i++) {
        int idx = t + 256*i;
        Ofs[idx >> 3][idx & 7] = Op[(size_t)(idx >> 3) * 32 + (idx & 7)];
    }
    if (t < 64) ((float2*)E8is)[t] = g_E8i[t];
    __syncthreads();
    int v = t >> 3, k = t & 7;
    // stage1: G[m] = sum_j conj(TV[m+8j][v]) * Of[m+8j][k]
    float2 gg[8];
    #pragma unroll
    for (int m = 0; m < 8; m++) {
        float gx = 0.f, gy = 0.f;
        #pragma unroll
        for (int j = 0; j < 8; j++) {
            int sx = m + 8*j;
            float2 o  = Ofs[sx][k];
            float2 tw = g_TV[sx * 32 + v];
            gx = fmaf(o.x, tw.x, fmaf( o.y, tw.y, gx));
            gy = fmaf(o.y, tw.x, fmaf(-o.x, tw.y, gy));
        }
        gg[m] = make_float2(gx, gy);
    }
    // stage2: Tmp[v+32a][k] = sum_m G[m] * e^{+2pi i m a/8}
    #pragma unroll
    for (int a = 0; a < 8; a++) {
        float tx = 0.f, ty = 0.f;
        #pragma unroll
        for (int m = 0; m < 8; m++) {
            float2 e = E8is[m][a];
            tx = fmaf(gg[m].x, e.x, fmaf(-gg[m].y, e.y, tx));
            ty = fmaf(gg[m].x, e.y, fmaf( gg[m].y, e.x, ty));
        }
        g_Tmp[((size_t)bco * 256 + v + 32*a) * 32 + kq * 8 + k] = make_float2(tx, ty);
    }
}

// ---- K5: inverse real DFT along W, radix split w = v + 32u, fused stages ----
__global__ void __launch_bounds__(256) k_irfftW(float* __restrict__ out) {
    __shared__ float2 Tms[32][32];   // [r][k]
    __shared__ float2 T1s[32][32];   // [k][v]
    __shared__ float2 E8is[8][8];
    int t = threadIdx.x;
    size_t rowBase = (size_t)blockIdx.x * 32;
    const float2* Tp = g_Tmp + rowBase * 32;
    #pragma unroll
    for (int i = 0; i < 4; i++) {
        int idx = t + 256*i;
        ((float2*)Tms)[idx] = Tp[idx];
        ((float2*)T1s)[idx] = g_TI[idx];
    }
    if (t < 64) ((float2*)E8is)[t] = g_E8i[t];
    __syncthreads();
    int v = t & 31, r4 = t >> 5;
    #pragma unroll
    for (int rr = 0; rr < 4; rr++) {
        int r = r4 + 8*rr;
        float2 G[8];
        #pragma unroll
        for (int m = 0; m < 8; m++) G[m] = make_float2(0.f, 0.f);
        #pragma unroll 8
        for (int k = 0; k < 32; k++) {
            float2 c  = Tms[r][k];
            float2 tw = T1s[k][v];
            int m = k & 7;
            G[m].x = fmaf(c.x, tw.x, fmaf(-c.y, tw.y, G[m].x));
            G[m].y = fmaf(c.x, tw.y, fmaf( c.y, tw.x, G[m].y));
        }
        #pragma unroll
        for (int u = 0; u < 8; u++) {
            float s = 0.f;
            #pragma unroll
            for (int m = 0; m < 8; m++) {
                float2 e = E8is[m][u];
                s = fmaf(G[m].x, e.x, fmaf(-G[m].y, e.y, s));
            }
            out[(rowBase + r) * 256 + 32*u + v] = s;
        }
    }
}

extern "C" void kernel_launch(void* const* d_in, const int* in_sizes, int n_in,
                              void* d_out, int out_size) {
    const float* x   = (const float*)d_in[0];
    const float* fs  = (const float*)d_in[1];
    const float* w0  = (const float*)d_in[2];
    const float* w1  = (const float*)d_in[3];
    const float* we0 = (const float*)d_in[4];
    const float* we1 = (const float*)d_in[5];
    float* out = (float*)d_out;

    k_init<<<17, 256>>>();
    k_fwdW<<<RTOT / 16, 256>>>(x);                       // 8192 blocks
    k_fwdH<<<Bsz * CIn * 4, 256>>>();                    // 2048 blocks
    k_mix<<<2 * 32 * 4, 256>>>(fs, w0, w1, we0, we1);    // 256 blocks
    k_invH<<<Bsz * COn * 4, 256>>>();                    // 2048 blocks
    k_irfftW<<<RTOT / 32, 256>>>(out);                   // 4096 blocks
}

// round 4
// speedup vs baseline: 1.5282x; 1.1612x over previous
#include <cuda_runtime.h>
#include <math.h>

// Problem constants
#define Bsz 16
#define CIn 32
#define COn 32
#define Hn  256
#define Wn  256
#define KM  32      // K0 = K1 = M = 32 (base and extra mode regions coincide)
#define SXn 64      // selected row-frequencies: 0..31 and 224..255
#define RTOT (Bsz*CIn*Hn)   // 131072 rows for the W-direction DFT

// ---- tables ----
__device__ float2 g_T32[32*32];   // [b][k]  e^{-2pi i k b/256}
__device__ float2 g_TV [64*32];   // [sx][v] e^{-2pi i kx(sx) v/256}
__device__ float2 g_TI [32*32];   // [k][v]  alpha_k * e^{+2pi i k v/256}  (alpha=(k?2:1)/256)
__device__ float2 g_E8 [8*8];     // [m][a]  e^{-2pi i m a/8}
__device__ float2 g_E8i[8*8];     // [m][a]  e^{+2pi i m a/8}

// ---- scratch ----
__device__ float2 g_Xw[(size_t)RTOT*KM];          // after fwd-W  [row][k]
__device__ float2 g_Xf[(size_t)Bsz*CIn*SXn*KM];   // after fwd-H  [b*32+ci][sx][k]
__device__ float2 g_Of[(size_t)Bsz*COn*SXn*KM];   // after mix    [b*32+co][sx][k]
__device__ float2 g_Tmp[(size_t)Bsz*COn*Hn*KM];   // after inv-H  [row][k]
__device__ float2 g_Wt [2*1024*1024];             // transposed W  [r][kxy][ci*32+co]
__device__ float2 g_Wet[2*1024*1024];             // transposed We [r][kxy][ci*32+co]

__global__ void k_init() {
    int t = blockIdx.x * blockDim.x + threadIdx.x;
    if (t < 1024) {                                 // g_T32
        int b = t >> 5, k = t & 31;
        float s, c; sincospif((float)(k * b) / 128.0f, &s, &c);
        g_T32[t] = make_float2(c, -s);
    }
    int t1 = t - 1024;
    if (t1 >= 0 && t1 < 2048) {                     // g_TV
        int sx = t1 >> 5, v = t1 & 31;
        int kx = (sx < 32) ? sx : (192 + sx);
        float s, c; sincospif((float)(kx * v) / 128.0f, &s, &c);
        g_TV[t1] = make_float2(c, -s);
    }
    int t2 = t1 - 2048;
    if (t2 >= 0 && t2 < 1024) {                     // g_TI
        int k = t2 >> 5, v = t2 & 31;
        float s, c; sincospif((float)(k * v) / 128.0f, &s, &c);
        float alpha = ((k == 0) ? 1.0f : 2.0f) * (1.0f / 256.0f);
        g_TI[t2] = make_float2(alpha * c, alpha * s);
    }
    int t3 = t2 - 1024;
    if (t3 >= 0 && t3 < 64) {                       // g_E8 / g_E8i
        int m = t3 >> 3, a = t3 & 7;
        float s, c; sincospif((float)(m * a) / 4.0f, &s, &c);
        g_E8 [t3] = make_float2(c, -s);
        g_E8i[t3] = make_float2(c,  s);
    }
}

// ---- K0b: transpose weights [p][kxy] -> [kxy][p]  (p = ci*32+co) ----
__global__ void __launch_bounds__(256) k_wtrans(const float* __restrict__ w0,
                                                const float* __restrict__ w1,
                                                const float* __restrict__ we0,
                                                const float* __restrict__ we1) {
    __shared__ float2 sm[32][33];
    int bid = blockIdx.x;
    int arr = bid >> 10;                  // 0:w0 1:w1 2:we0 3:we1
    int tile = bid & 1023;
    int I = tile >> 5, J = tile & 31;     // p-tile, q-tile
    const float2* src = (const float2*)((arr == 0) ? w0 : (arr == 1) ? w1 : (arr == 2) ? we0 : we1);
    float2* dst = (arr < 2) ? (g_Wt + (size_t)arr * 1024 * 1024)
                            : (g_Wet + (size_t)(arr - 2) * 1024 * 1024);
    int t = threadIdx.x;
    int c = t & 31, rq = t >> 5;
    #pragma unroll
    for (int i = 0; i < 4; i++) {
        int p = I * 32 + rq + 8 * i;
        sm[rq + 8 * i][c] = src[(size_t)p * 1024 + J * 32 + c];
    }
    __syncthreads();
    #pragma unroll
    for (int i = 0; i < 4; i++) {
        int q = J * 32 + rq + 8 * i;
        dst[(size_t)q * 1024 + I * 32 + c] = sm[c][rq + 8 * i];
    }
}

// ---- K1: fwd DFT along W, radix split w = b + 32a ----
__global__ void __launch_bounds__(256) k_fwdW(const float* __restrict__ x) {
    __shared__ float  Xs[16][256];
    __shared__ float2 Ys[16][32][5];      // [r][b][m], m=0..4 (Hermitian)
    __shared__ float2 T32s[32][32];       // [b][k]
    __shared__ float2 E8s[5][8];
    int t = threadIdx.x;
    size_t rowBase = (size_t)blockIdx.x * 16;
    const float4* xg = (const float4*)(x + rowBase * 256);
    float4* xs4 = (float4*)&Xs[0][0];
    #pragma unroll
    for (int i = 0; i < 4; i++) xs4[t + 256*i] = xg[t + 256*i];
    #pragma unroll
    for (int i = 0; i < 4; i++) ((float2*)T32s)[t + 256*i] = g_T32[t + 256*i];
    if (t < 40) ((float2*)E8s)[t] = g_E8[t];
    __syncthreads();
    // stage1: 8-pt real DFT per (r,b); 512 tasks, 2/thread
    #pragma unroll
    for (int it = 0; it < 2; it++) {
        int task = t + 256*it;
        int r = task >> 5, b = task & 31;
        float xa[8];
        #pragma unroll
        for (int a = 0; a < 8; a++) xa[a] = Xs[r][b + 32*a];
        #pragma unroll
        for (int m = 0; m < 5; m++) {
            float yr = 0.f, yi = 0.f;
            #pragma unroll
            for (int a = 0; a < 8; a++) {
                float2 e = E8s[m][a];
                yr = fmaf(xa[a], e.x, yr);
                yi = fmaf(xa[a], e.y, yi);
            }
            Ys[r][b][m] = make_float2(yr, yi);
        }
    }
    __syncthreads();
    // stage2: C[k] = sum_b T32[b][k] * Y[b][k&7]  (conj fold for m>4)
    int k = t & 31, r0 = t >> 5;
    int m0 = k & 7;
    int sel = (m0 > 4) ? (8 - m0) : m0;
    float sgn = (m0 > 4) ? -1.f : 1.f;
    #pragma unroll
    for (int rr = 0; rr < 2; rr++) {
        int r = r0 + 8*rr;
        float ax = 0.f, ay = 0.f;
        #pragma unroll 8
        for (int b = 0; b < 32; b++) {
            float2 y  = Ys[r][b][sel];
            float  yi = sgn * y.y;
            float2 tw = T32s[b][k];
            ax = fmaf(y.x, tw.x, fmaf(-yi, tw.y, ax));
            ay = fmaf(y.x, tw.y, fmaf( yi, tw.x, ay));
        }
        g_Xw[(rowBase + r) * 32 + k] = make_float2(ax, ay);
    }
}

// ---- K2: fwd DFT along H on 64 selected kx, radix split h = v + 32a ----
__global__ void __launch_bounds__(256) k_fwdH() {
    __shared__ float2 Xs[256][8];         // [h][k] for this k-quarter
    __shared__ float2 Ys[32][8][8];       // [v][m][k]
    __shared__ float2 E8s[8][8];
    int t = threadIdx.x;
    int bci = blockIdx.x >> 2, kq = blockIdx.x & 3;
    const float2* Xp = g_Xw + (size_t)bci * 256 * 32 + kq * 8;
    #pragma unroll
    for (int i = 0; i < 8; i++) {
        int idx = t + 256*i;
        Xs[idx >> 3][idx & 7] = Xp[(size_t)(idx >> 3) * 32 + (idx & 7)];
    }
    if (t < 64) ((float2*)E8s)[t] = g_E8[t];
    __syncthreads();
    // stage1: Y[v][m][k] = sum_a X[v+32a][k] * E8[m][a]
    int v = t >> 3, k = t & 7;
    {
        float2 xa[8];
        #pragma unroll
        for (int a = 0; a < 8; a++) xa[a] = Xs[v + 32*a][k];
        #pragma unroll
        for (int m = 0; m < 8; m++) {
            float yr = 0.f, yi = 0.f;
            #pragma unroll
            for (int a = 0; a < 8; a++) {
                float2 e = E8s[m][a];
                yr = fmaf(xa[a].x, e.x, fmaf(-xa[a].y, e.y, yr));
                yi = fmaf(xa[a].x, e.y, fmaf( xa[a].y, e.x, yi));
            }
            Ys[v][m][k] = make_float2(yr, yi);
        }
    }
    __syncthreads();
    // stage2: out[sx][k] = (1/256) sum_v TV[sx][v] * Y[v][sx&7][k]; sx2 and sx2+32 share m
    int k2 = t & 7, sx2 = t >> 3;
    int m = sx2 & 7;
    float a0x = 0.f, a0y = 0.f, a1x = 0.f, a1y = 0.f;
    #pragma unroll 8
    for (int vv = 0; vv < 32; vv++) {
        float2 y  = Ys[vv][m][k2];
        float2 t0 = g_TV[sx2 * 32 + vv];
        float2 t1 = g_TV[(sx2 + 32) * 32 + vv];
        a0x = fmaf(y.x, t0.x, fmaf(-y.y, t0.y, a0x));
        a0y = fmaf(y.x, t0.y, fmaf( y.y, t0.x, a0y));
        a1x = fmaf(y.x, t1.x, fmaf(-y.y, t1.y, a1x));
        a1y = fmaf(y.x, t1.y, fmaf( y.y, t1.x, a1y));
    }
    const float nrm = 1.0f / 256.0f;
    g_Xf[((size_t)bci * 64 + sx2)      * 32 + kq * 8 + k2] = make_float2(a0x * nrm, a0y * nrm);
    g_Xf[((size_t)bci * 64 + sx2 + 32) * 32 + kq * 8 + k2] = make_float2(a1x * nrm, a1y * nrm);
}

// ---- K3: channel mixing; weights pre-transposed, all smem-staged ----
__global__ void __launch_bounds__(256) k_mix(const float* __restrict__ fs) {
    __shared__ float2 Ws[1024];
    __shared__ float2 Wes[1024];
    __shared__ float2 Xs[16][32];
    __shared__ float  ssm[16];
    int bid = blockIdx.x;
    int r = bid >> 10, kxy = bid & 1023;
    int kx = kxy >> 5, ky = kxy & 31;
    int sxg = r * 32 + kx;
    const float2* Wp  = g_Wt  + ((size_t)r << 20) + ((size_t)kxy << 10);
    const float2* Wep = g_Wet + ((size_t)r << 20) + ((size_t)kxy << 10);
    int t = threadIdx.x;
    #pragma unroll
    for (int i = 0; i < 4; i++) {
        Ws [t + 256*i] = Wp [t + 256*i];
        Wes[t + 256*i] = Wep[t + 256*i];
    }
    #pragma unroll
    for (int i = 0; i < 2; i++) {
        int p = t + 256*i;                           // p = b*32 + ci
        Xs[p >> 5][p & 31] = g_Xf[((size_t)p * 64 + sxg) * 32 + ky];
    }
    if (t < 16) {
        int idx;                                     // hierarchical quadrant (LEVEL0=3, KAPPA=8)
        if (kx < 8 && ky < 8)        idx = 0;
        else if (kx < 16 && ky < 16) idx = (kx < 8) ? 1 : ((ky < 8) ? 2 : 3);
        else                         idx = (kx < 16) ? 4 : ((ky < 16) ? 5 : 6);
        ssm[t] = fs[t * 7 + idx];
    }
    __syncthreads();
    int co = t & 31, bh = t >> 5;
    float sb0 = ssm[bh], sb1 = ssm[bh + 8];
    float a0x = 0.f, a0y = 0.f, a1x = 0.f, a1y = 0.f;
    #pragma unroll 8
    for (int ci = 0; ci < 32; ci++) {
        float2 w  = Ws [ci * 32 + co];
        float2 we = Wes[ci * 32 + co];
        float2 x0 = Xs[bh][ci];                      // warp-uniform -> broadcast
        float2 x1 = Xs[bh + 8][ci];
        float wr0 = fmaf(sb0, we.x, w.x), wi0 = fmaf(sb0, we.y, w.y);
        float wr1 = fmaf(sb1, we.x, w.x), wi1 = fmaf(sb1, we.y, w.y);
        a0x = fmaf(x0.x, wr0, fmaf(-x0.y, wi0, a0x));
        a0y = fmaf(x0.x, wi0, fmaf( x0.y, wr0, a0y));
        a1x = fmaf(x1.x, wr1, fmaf(-x1.y, wi1, a1x));
        a1y = fmaf(x1.x, wi1, fmaf( x1.y, wr1, a1y));
    }
    g_Of[(((size_t)bh       * 32 + co) * 64 + sxg) * 32 + ky] = make_float2(a0x, a0y);
    g_Of[(((size_t)(bh + 8) * 32 + co) * 64 + sxg) * 32 + ky] = make_float2(a1x, a1y);
}

// ---- K4: inverse DFT along H, radix split h = v + 32a, stages fused per-thread ----
__global__ void __launch_bounds__(256) k_invH() {
    __shared__ float2 Ofs[64][8];
    __shared__ float2 E8is[8][8];
    int t = threadIdx.x;
    int bco = blockIdx.x >> 2, kq = blockIdx.x & 3;
    const float2* Op = g_Of + (size_t)bco * 64 * 32 + kq * 8;
    #pragma unroll
    for (int i = 0; i < 2; i++) {
        int idx = t + 256*i;
        Ofs[idx >> 3][idx & 7] = Op[(size_t)(idx >> 3) * 32 + (idx & 7)];
    }
    if (t < 64) ((float2*)E8is)[t] = g_E8i[t];
    __syncthreads();
    int v = t >> 3, k = t & 7;
    // stage1: G[m] = sum_j conj(TV[m+8j][v]) * Of[m+8j][k]
    float2 gg[8];
    #pragma unroll
    for (int m = 0; m < 8; m++) {
        float gx = 0.f, gy = 0.f;
        #pragma unroll
        for (int j = 0; j < 8; j++) {
            int sx = m + 8*j;
            float2 o  = Ofs[sx][k];
            float2 tw = g_TV[sx * 32 + v];
            gx = fmaf(o.x, tw.x, fmaf( o.y, tw.y, gx));
            gy = fmaf(o.y, tw.x, fmaf(-o.x, tw.y, gy));
        }
        gg[m] = make_float2(gx, gy);
    }
    // stage2: Tmp[v+32a][k] = sum_m G[m] * e^{+2pi i m a/8}
    #pragma unroll
    for (int a = 0; a < 8; a++) {
        float tx = 0.f, ty = 0.f;
        #pragma unroll
        for (int m = 0; m < 8; m++) {
            float2 e = E8is[m][a];
            tx = fmaf(gg[m].x, e.x, fmaf(-gg[m].y, e.y, tx));
            ty = fmaf(gg[m].x, e.y, fmaf( gg[m].y, e.x, ty));
        }
        g_Tmp[((size_t)bco * 256 + v + 32*a) * 32 + kq * 8 + k] = make_float2(tx, ty);
    }
}

// ---- K5: inverse real DFT along W, radix split w = v + 32u, fused stages ----
__global__ void __launch_bounds__(256) k_irfftW(float* __restrict__ out) {
    __shared__ float2 Tms[32][32];   // [r][k]
    __shared__ float2 T1s[32][32];   // [k][v]
    __shared__ float2 E8is[8][8];
    int t = threadIdx.x;
    size_t rowBase = (size_t)blockIdx.x * 32;
    const float2* Tp = g_Tmp + rowBase * 32;
    #pragma unroll
    for (int i = 0; i < 4; i++) {
        int idx = t + 256*i;
        ((float2*)Tms)[idx] = Tp[idx];
        ((float2*)T1s)[idx] = g_TI[idx];
    }
    if (t < 64) ((float2*)E8is)[t] = g_E8i[t];
    __syncthreads();
    int v = t & 31, r4 = t >> 5;
    #pragma unroll
    for (int rr = 0; rr < 4; rr++) {
        int r = r4 + 8*rr;
        float2 G[8];
        #pragma unroll
        for (int m = 0; m < 8; m++) G[m] = make_float2(0.f, 0.f);
        #pragma unroll 8
        for (int k = 0; k < 32; k++) {
            float2 c  = Tms[r][k];
            float2 tw = T1s[k][v];
            int m = k & 7;
            G[m].x = fmaf(c.x, tw.x, fmaf(-c.y, tw.y, G[m].x));
            G[m].y = fmaf(c.x, tw.y, fmaf( c.y, tw.x, G[m].y));
        }
        #pragma unroll
        for (int u = 0; u < 8; u++) {
            float s = 0.f;
            #pragma unroll
            for (int m = 0; m < 8; m++) {
                float2 e = E8is[m][u];
                s = fmaf(G[m].x, e.x, fmaf(-G[m].y, e.y, s));
            }
            out[(rowBase + r) * 256 + 32*u + v] = s;
        }
    }
}

extern "C" void kernel_launch(void* const* d_in, const int* in_sizes, int n_in,
                              void* d_out, int out_size) {
    const float* x   = (const float*)d_in[0];
    const float* fs  = (const float*)d_in[1];
    const float* w0  = (const float*)d_in[2];
    const float* w1  = (const float*)d_in[3];
    const float* we0 = (const float*)d_in[4];
    const float* we1 = (const float*)d_in[5];
    float* out = (float*)d_out;

    k_init<<<17, 256>>>();
    k_wtrans<<<4096, 256>>>(w0, w1, we0, we1);           // weight transpose
    k_fwdW<<<RTOT / 16, 256>>>(x);                       // 8192 blocks
    k_fwdH<<<Bsz * CIn * 4, 256>>>();                    // 2048 blocks
    k_mix<<<2 * 1024, 256>>>(fs);                        // 2048 blocks
    k_invH<<<Bsz * COn * 4, 256>>>();                    // 2048 blocks
    k_irfftW<<<RTOT / 32, 256>>>(out);                   // 4096 blocks
}

// round 6
// speedup vs baseline: 2.0503x; 1.3417x over previous
#include <cuda_runtime.h>
#include <cuda_bf16.h>
#include <math.h>
#include <stdint.h>

// Problem constants
#define Bsz 16
#define CIn 32
#define COn 32
#define Hn  256
#define Wn  256
#define KM  32
#define SXn 64
#define RTOT (Bsz*CIn*Hn)   // 131072 rows

// ============================ tables / scratch ============================
__device__ float2 g_TV [64*32];   // [sx][v] e^{-2pi i kx(sx) v/256}
__device__ float2 g_E8 [8*8];
__device__ float2 g_E8i[8*8];
// fwdW basis  [kc(4)][n(64)][72pad]  bf16 hi/lo;  value(n,w=kc*64+kk)
__device__ __align__(16) __nv_bfloat16 g_BWh[4*64*72], g_BWl[4*64*72];
// irfft basis [nh(2)][wn(128)][72pad] bf16 hi/lo; value(w=nh*128+wn, j)
__device__ __align__(16) __nv_bfloat16 g_BIh[2*128*72], g_BIl[2*128*72];

__device__ float2 g_Xw[(size_t)RTOT*KM];
__device__ float2 g_Xf[(size_t)Bsz*CIn*SXn*KM];
__device__ float2 g_Of[(size_t)Bsz*COn*SXn*KM];
__device__ float2 g_Tmp[(size_t)Bsz*COn*Hn*KM];
__device__ float2 g_Wt [2*1024*1024];
__device__ float2 g_Wet[2*1024*1024];

// ============================ helpers ============================
__device__ __forceinline__ uint32_t pack_bf(__nv_bfloat16 a, __nv_bfloat16 b) {
    return (uint32_t)__bfloat16_as_ushort(a) | ((uint32_t)__bfloat16_as_ushort(b) << 16);
}
__device__ __forceinline__ void split_bf(float v, __nv_bfloat16& h, __nv_bfloat16& l) {
    h = __float2bfloat16(v);
    l = __float2bfloat16(v - __bfloat162float(h));
}
__device__ __forceinline__ void mma16816(float* c, const uint32_t* a, const uint32_t* b) {
    asm volatile("mma.sync.aligned.m16n8k16.row.col.f32.bf16.bf16.f32 "
        "{%0,%1,%2,%3}, {%4,%5,%6,%7}, {%8,%9}, {%0,%1,%2,%3};"
        : "+f"(c[0]), "+f"(c[1]), "+f"(c[2]), "+f"(c[3])
        : "r"(a[0]), "r"(a[1]), "r"(a[2]), "r"(a[3]), "r"(b[0]), "r"(b[1]));
}

__global__ void k_init() {
    int t = blockIdx.x * blockDim.x + threadIdx.x;
    if (t < 2048) {                     // g_TV
        int sx = t >> 5, v = t & 31;
        int kx = (sx < 32) ? sx : (192 + sx);
        float s, c; sincospif((float)(kx * v) / 128.0f, &s, &c);
        g_TV[t] = make_float2(c, -s);
    }
    int t1 = t - 2048;
    if (t1 >= 0 && t1 < 64) {           // E8 / E8i
        int m = t1 >> 3, a = t1 & 7;
        float s, c; sincospif((float)(m * a) / 4.0f, &s, &c);
        g_E8 [t1] = make_float2(c, -s);
        g_E8i[t1] = make_float2(c,  s);
    }
    int t2 = t1 - 64;
    if (t2 >= 0 && t2 < 4*64*72) {      // fwdW basis
        int kc = t2 / (64*72);
        int rem = t2 % (64*72);
        int n = rem / 72, kk = rem % 72;
        float v = 0.f;
        if (kk < 64) {
            int w = kc * 64 + kk;
            float s, c; sincospif((float)((n >> 1) * w) / 128.0f, &s, &c);
            v = (n & 1) ? -s : c;
        }
        __nv_bfloat16 h, l; split_bf(v, h, l);
        g_BWh[t2] = h; g_BWl[t2] = l;
    }
    int t3 = t2 - 4*64*72;
    if (t3 >= 0 && t3 < 2*128*72) {     // irfft basis
        int nh = t3 / (128*72);
        int rem = t3 % (128*72);
        int wn = rem / 72, j = rem % 72;
        float v = 0.f;
        if (j < 64) {
            int w = nh * 128 + wn;
            int q = j >> 1;
            float s, c; sincospif((float)(q * w) / 128.0f, &s, &c);
            float alpha = ((q == 0) ? 1.0f : 2.0f) * (1.0f / 256.0f);
            v = (j & 1) ? -alpha * s : alpha * c;
        }
        __nv_bfloat16 h, l; split_bf(v, h, l);
        g_BIh[t3] = h; g_BIl[t3] = l;
    }
}

// ---- K0b: transpose weights [p][kxy] -> [kxy][p] ----
__global__ void __launch_bounds__(256) k_wtrans(const float* __restrict__ w0,
                                                const float* __restrict__ w1,
                                                const float* __restrict__ we0,
                                                const float* __restrict__ we1) {
    __shared__ float2 sm[32][33];
    int bid = blockIdx.x;
    int arr = bid >> 10;
    int tile = bid & 1023;
    int I = tile >> 5, J = tile & 31;
    const float2* src = (const float2*)((arr == 0) ? w0 : (arr == 1) ? w1 : (arr == 2) ? we0 : we1);
    float2* dst = (arr < 2) ? (g_Wt + (size_t)arr * 1024 * 1024)
                            : (g_Wet + (size_t)(arr - 2) * 1024 * 1024);
    int t = threadIdx.x;
    int c = t & 31, rq = t >> 5;
    #pragma unroll
    for (int i = 0; i < 4; i++)
        sm[rq + 8 * i][c] = src[(size_t)(I * 32 + rq + 8 * i) * 1024 + J * 32 + c];
    __syncthreads();
    #pragma unroll
    for (int i = 0; i < 4; i++)
        dst[(size_t)(J * 32 + rq + 8 * i) * 1024 + I * 32 + c] = sm[c][rq + 8 * i];
}

// ============== K1: fwd DFT along W via mma.sync bf16 (D[row][64] = X[row][256]·B^T) ==============
// CTA: 128 rows, 256 thr (8 warps, warp = 16 rows x 64 modes). K chunked 4x64.
#define FW_SMEM 55296
__global__ void __launch_bounds__(256) k_fwdW_m(const float* __restrict__ x) {
    extern __shared__ unsigned char smem[];
    __nv_bfloat16* Ah = (__nv_bfloat16*)(smem);
    __nv_bfloat16* Al = (__nv_bfloat16*)(smem + 18432);
    __nv_bfloat16* Bh = (__nv_bfloat16*)(smem + 36864);
    __nv_bfloat16* Bl = (__nv_bfloat16*)(smem + 46080);
    int tid = threadIdx.x, lane = tid & 31, wid = tid >> 5;
    int g = lane >> 2, t4 = lane & 3;
    size_t rowBase = (size_t)blockIdx.x * 128;
    int m0 = wid * 16;
    float acc[8][4];
    #pragma unroll
    for (int nt = 0; nt < 8; nt++)
        #pragma unroll
        for (int i = 0; i < 4; i++) acc[nt][i] = 0.f;

    const float4* xg = (const float4*)x;
    for (int kc = 0; kc < 4; kc++) {
        __syncthreads();
        // stage A chunk: 128 rows x 64 cols
        #pragma unroll
        for (int i = 0; i < 8; i++) {
            int idx = tid + 256 * i;                  // 0..2047
            int r = idx >> 4, c4 = idx & 15;
            float4 v = xg[(rowBase + r) * 64 + kc * 16 + c4];
            __nv_bfloat16 h0, h1, h2, h3, l0, l1, l2, l3;
            split_bf(v.x, h0, l0); split_bf(v.y, h1, l1);
            split_bf(v.z, h2, l2); split_bf(v.w, h3, l3);
            uint2 hp = make_uint2(pack_bf(h0, h1), pack_bf(h2, h3));
            uint2 lp = make_uint2(pack_bf(l0, l1), pack_bf(l2, l3));
            *(uint2*)(Ah + r * 72 + c4 * 4) = hp;
            *(uint2*)(Al + r * 72 + c4 * 4) = lp;
        }
        // stage B chunk: contiguous copy of padded [64][72]
        {
            const uint4* sh = ((const uint4*)g_BWh) + kc * 576;
            const uint4* sl = ((const uint4*)g_BWl) + kc * 576;
            uint4* dh = (uint4*)Bh; uint4* dl = (uint4*)Bl;
            for (int i = tid; i < 576; i += 256) { dh[i] = sh[i]; dl[i] = sl[i]; }
        }
        __syncthreads();
        #pragma unroll
        for (int ks = 0; ks < 4; ks++) {
            int aoff = (m0 + g) * 72 + ks * 16 + 2 * t4;
            uint32_t ah[4], al[4];
            ah[0] = *(const uint32_t*)(Ah + aoff);
            ah[1] = *(const uint32_t*)(Ah + aoff + 8 * 72);
            ah[2] = *(const uint32_t*)(Ah + aoff + 8);
            ah[3] = *(const uint32_t*)(Ah + aoff + 8 * 72 + 8);
            al[0] = *(const uint32_t*)(Al + aoff);
            al[1] = *(const uint32_t*)(Al + aoff + 8 * 72);
            al[2] = *(const uint32_t*)(Al + aoff + 8);
            al[3] = *(const uint32_t*)(Al + aoff + 8 * 72 + 8);
            #pragma unroll
            for (int nt = 0; nt < 8; nt++) {
                int boff = (nt * 8 + g) * 72 + ks * 16 + 2 * t4;
                uint32_t bh[2], bl[2];
                bh[0] = *(const uint32_t*)(Bh + boff);
                bh[1] = *(const uint32_t*)(Bh + boff + 8);
                bl[0] = *(const uint32_t*)(Bl + boff);
                bl[1] = *(const uint32_t*)(Bl + boff + 8);
                mma16816(acc[nt], ah, bh);
                mma16816(acc[nt], ah, bl);
                mma16816(acc[nt], al, bh);
            }
        }
    }
    // epilogue: C frags -> g_Xw[row][mode] (float2 pairs, cols 2t4 even)
    float2* gx = (float2*)g_Xw;
    #pragma unroll
    for (int nt = 0; nt < 8; nt++) {
        int col = nt * 4 + t4;
        gx[(rowBase + m0 + g) * 32 + col]     = make_float2(acc[nt][0], acc[nt][1]);
        gx[(rowBase + m0 + g + 8) * 32 + col] = make_float2(acc[nt][2], acc[nt][3]);
    }
}

// ---- K2: fwd DFT along H (scalar radix-8) ----
__global__ void __launch_bounds__(256) k_fwdH() {
    __shared__ float2 Xs[256][8];
    __shared__ float2 Ys[32][8][8];
    __shared__ float2 E8s[8][8];
    int t = threadIdx.x;
    int bci = blockIdx.x >> 2, kq = blockIdx.x & 3;
    const float2* Xp = g_Xw + (size_t)bci * 256 * 32 + kq * 8;
    #pragma unroll
    for (int i = 0; i < 8; i++) {
        int idx = t + 256*i;
        Xs[idx >> 3][idx & 7] = Xp[(size_t)(idx >> 3) * 32 + (idx & 7)];
    }
    if (t < 64) ((float2*)E8s)[t] = g_E8[t];
    __syncthreads();
    int v = t >> 3, k = t & 7;
    {
        float2 xa[8];
        #pragma unroll
        for (int a = 0; a < 8; a++) xa[a] = Xs[v + 32*a][k];
        #pragma unroll
        for (int m = 0; m < 8; m++) {
            float yr = 0.f, yi = 0.f;
            #pragma unroll
            for (int a = 0; a < 8; a++) {
                float2 e = E8s[m][a];
                yr = fmaf(xa[a].x, e.x, fmaf(-xa[a].y, e.y, yr));
                yi = fmaf(xa[a].x, e.y, fmaf( xa[a].y, e.x, yi));
            }
            Ys[v][m][k] = make_float2(yr, yi);
        }
    }
    __syncthreads();
    int k2 = t & 7, sx2 = t >> 3;
    int m = sx2 & 7;
    float a0x = 0.f, a0y = 0.f, a1x = 0.f, a1y = 0.f;
    #pragma unroll 8
    for (int vv = 0; vv < 32; vv++) {
        float2 y  = Ys[vv][m][k2];
        float2 t0 = g_TV[sx2 * 32 + vv];
        float2 t1 = g_TV[(sx2 + 32) * 32 + vv];
        a0x = fmaf(y.x, t0.x, fmaf(-y.y, t0.y, a0x));
        a0y = fmaf(y.x, t0.y, fmaf( y.y, t0.x, a0y));
        a1x = fmaf(y.x, t1.x, fmaf(-y.y, t1.y, a1x));
        a1y = fmaf(y.x, t1.y, fmaf( y.y, t1.x, a1y));
    }
    const float nrm = 1.0f / 256.0f;
    g_Xf[((size_t)bci * 64 + sx2)      * 32 + kq * 8 + k2] = make_float2(a0x * nrm, a0y * nrm);
    g_Xf[((size_t)bci * 64 + sx2 + 32) * 32 + kq * 8 + k2] = make_float2(a1x * nrm, a1y * nrm);
}

// ---- K3: channel mixing ----
__global__ void __launch_bounds__(256) k_mix(const float* __restrict__ fs) {
    __shared__ float2 Ws[1024];
    __shared__ float2 Wes[1024];
    __shared__ float2 Xs[16][32];
    __shared__ float  ssm[16];
    int bid = blockIdx.x;
    int r = bid >> 10, kxy = bid & 1023;
    int kx = kxy >> 5, ky = kxy & 31;
    int sxg = r * 32 + kx;
    const float2* Wp  = g_Wt  + ((size_t)r << 20) + ((size_t)kxy << 10);
    const float2* Wep = g_Wet + ((size_t)r << 20) + ((size_t)kxy << 10);
    int t = threadIdx.x;
    #pragma unroll
    for (int i = 0; i < 4; i++) {
        Ws [t + 256*i] = Wp [t + 256*i];
        Wes[t + 256*i] = Wep[t + 256*i];
    }
    #pragma unroll
    for (int i = 0; i < 2; i++) {
        int p = t + 256*i;
        Xs[p >> 5][p & 31] = g_Xf[((size_t)p * 64 + sxg) * 32 + ky];
    }
    if (t < 16) {
        int idx;
        if (kx < 8 && ky < 8)        idx = 0;
        else if (kx < 16 && ky < 16) idx = (kx < 8) ? 1 : ((ky < 8) ? 2 : 3);
        else                         idx = (kx < 16) ? 4 : ((ky < 16) ? 5 : 6);
        ssm[t] = fs[t * 7 + idx];
    }
    __syncthreads();
    int co = t & 31, bh = t >> 5;
    float sb0 = ssm[bh], sb1 = ssm[bh + 8];
    float a0x = 0.f, a0y = 0.f, a1x = 0.f, a1y = 0.f;
    #pragma unroll 8
    for (int ci = 0; ci < 32; ci++) {
        float2 w  = Ws [ci * 32 + co];
        float2 we = Wes[ci * 32 + co];
        float2 x0 = Xs[bh][ci];
        float2 x1 = Xs[bh + 8][ci];
        float wr0 = fmaf(sb0, we.x, w.x), wi0 = fmaf(sb0, we.y, w.y);
        float wr1 = fmaf(sb1, we.x, w.x), wi1 = fmaf(sb1, we.y, w.y);
        a0x = fmaf(x0.x, wr0, fmaf(-x0.y, wi0, a0x));
        a0y = fmaf(x0.x, wi0, fmaf( x0.y, wr0, a0y));
        a1x = fmaf(x1.x, wr1, fmaf(-x1.y, wi1, a1x));
        a1y = fmaf(x1.x, wi1, fmaf( x1.y, wr1, a1y));
    }
    g_Of[(((size_t)bh       * 32 + co) * 64 + sxg) * 32 + ky] = make_float2(a0x, a0y);
    g_Of[(((size_t)(bh + 8) * 32 + co) * 64 + sxg) * 32 + ky] = make_float2(a1x, a1y);
}

// ---- K4: inverse DFT along H (scalar radix-8) ----
__global__ void __launch_bounds__(256) k_invH() {
    __shared__ float2 Ofs[64][8];
    __shared__ float2 E8is[8][8];
    int t = threadIdx.x;
    int bco = blockIdx.x >> 2, kq = blockIdx.x & 3;
    const float2* Op = g_Of + (size_t)bco * 64 * 32 + kq * 8;
    #pragma unroll
    for (int i = 0; i < 2; i++) {
        int idx = t + 256*i;
        Ofs[idx >> 3][idx & 7] = Op[(size_t)(idx >> 3) * 32 + (idx & 7)];
    }
    if (t < 64) ((float2*)E8is)[t] = g_E8i[t];
    __syncthreads();
    int v = t >> 3, k = t & 7;
    float2 gg[8];
    #pragma unroll
    for (int m = 0; m < 8; m++) {
        float gx = 0.f, gy = 0.f;
        #pragma unroll
        for (int j = 0; j < 8; j++) {
            int sx = m + 8*j;
            float2 o  = Ofs[sx][k];
            float2 tw = g_TV[sx * 32 + v];
            gx = fmaf(o.x, tw.x, fmaf( o.y, tw.y, gx));
            gy = fmaf(o.y, tw.x, fmaf(-o.x, tw.y, gy));
        }
        gg[m] = make_float2(gx, gy);
    }
    #pragma unroll
    for (int a = 0; a < 8; a++) {
        float tx = 0.f, ty = 0.f;
        #pragma unroll
        for (int m = 0; m < 8; m++) {
            float2 e = E8is[m][a];
            tx = fmaf(gg[m].x, e.x, fmaf(-gg[m].y, e.y, tx));
            ty = fmaf(gg[m].x, e.y, fmaf( gg[m].y, e.x, ty));
        }
        g_Tmp[((size_t)bco * 256 + v + 32*a) * 32 + kq * 8 + k] = make_float2(tx, ty);
    }
}

// ============== K5: inverse real DFT along W via mma.sync bf16 (out[row][w] = Tmp[row][64]·BI^T) ==============
// CTA: 128 rows x 128 w-half, 256 thr (8 warps, warp = 32 rows x 64 w). K=64.
#define IR_SMEM 73728
__global__ void __launch_bounds__(256) k_irfftW_m(float* __restrict__ out) {
    extern __shared__ unsigned char smem[];
    __nv_bfloat16* Ah = (__nv_bfloat16*)(smem);
    __nv_bfloat16* Al = (__nv_bfloat16*)(smem + 18432);
    __nv_bfloat16* Bh = (__nv_bfloat16*)(smem + 36864);
    __nv_bfloat16* Bl = (__nv_bfloat16*)(smem + 55296);
    int tid = threadIdx.x, lane = tid & 31, wid = tid >> 5;
    int g = lane >> 2, t4 = lane & 3;
    int rg = blockIdx.x >> 1, nh = blockIdx.x & 1;
    size_t rowBase = (size_t)rg * 128;

    // stage A: 128 rows x 64 floats from g_Tmp
    const float4* ag = (const float4*)g_Tmp;
    #pragma unroll
    for (int i = 0; i < 8; i++) {
        int idx = tid + 256 * i;
        int r = idx >> 4, c4 = idx & 15;
        float4 v = ag[(rowBase + r) * 16 + c4];
        __nv_bfloat16 h0, h1, h2, h3, l0, l1, l2, l3;
        split_bf(v.x, h0, l0); split_bf(v.y, h1, l1);
        split_bf(v.z, h2, l2); split_bf(v.w, h3, l3);
        *(uint2*)(Ah + r * 72 + c4 * 4) = make_uint2(pack_bf(h0, h1), pack_bf(h2, h3));
        *(uint2*)(Al + r * 72 + c4 * 4) = make_uint2(pack_bf(l0, l1), pack_bf(l2, l3));
    }
    // stage B: padded [128][72] half
    {
        const uint4* sh = ((const uint4*)g_BIh) + nh * 1152;
        const uint4* sl = ((const uint4*)g_BIl) + nh * 1152;
        uint4* dh = (uint4*)Bh; uint4* dl = (uint4*)Bl;
        for (int i = tid; i < 1152; i += 256) { dh[i] = sh[i]; dl[i] = sl[i]; }
    }
    __syncthreads();

    int m0 = (wid >> 1) * 32;
    int n0 = (wid & 1) * 64;
    float acc[2][8][4];
    #pragma unroll
    for (int mt = 0; mt < 2; mt++)
        #pragma unroll
        for (int nt = 0; nt < 8; nt++)
            #pragma unroll
            for (int i = 0; i < 4; i++) acc[mt][nt][i] = 0.f;

    #pragma unroll
    for (int ks = 0; ks < 4; ks++) {
        uint32_t ah[2][4], al[2][4];
        #pragma unroll
        for (int mt = 0; mt < 2; mt++) {
            int aoff = (m0 + mt * 16 + g) * 72 + ks * 16 + 2 * t4;
            ah[mt][0] = *(const uint32_t*)(Ah + aoff);
            ah[mt][1] = *(const uint32_t*)(Ah + aoff + 8 * 72);
            ah[mt][2] = *(const uint32_t*)(Ah + aoff + 8);
            ah[mt][3] = *(const uint32_t*)(Ah + aoff + 8 * 72 + 8);
            al[mt][0] = *(const uint32_t*)(Al + aoff);
            al[mt][1] = *(const uint32_t*)(Al + aoff + 8 * 72);
            al[mt][2] = *(const uint32_t*)(Al + aoff + 8);
            al[mt][3] = *(const uint32_t*)(Al + aoff + 8 * 72 + 8);
        }
        #pragma unroll
        for (int nt = 0; nt < 8; nt++) {
            int boff = (n0 + nt * 8 + g) * 72 + ks * 16 + 2 * t4;
            uint32_t bh[2], bl[2];
            bh[0] = *(const uint32_t*)(Bh + boff);
            bh[1] = *(const uint32_t*)(Bh + boff + 8);
            bl[0] = *(const uint32_t*)(Bl + boff);
            bl[1] = *(const uint32_t*)(Bl + boff + 8);
            #pragma unroll
            for (int mt = 0; mt < 2; mt++) {
                mma16816(acc[mt][nt], ah[mt], bh);
                mma16816(acc[mt][nt], ah[mt], bl);
                mma16816(acc[mt][nt], al[mt], bh);
            }
        }
    }
    // epilogue: direct stores out[row][w]
    #pragma unroll
    for (int mt = 0; mt < 2; mt++) {
        size_t r0 = rowBase + m0 + mt * 16 + g;
        #pragma unroll
        for (int nt = 0; nt < 8; nt++) {
            int col = nh * 128 + n0 + nt * 8 + 2 * t4;
            *(float2*)(out + r0 * 256 + col)       = make_float2(acc[mt][nt][0], acc[mt][nt][1]);
            *(float2*)(out + (r0 + 8) * 256 + col) = make_float2(acc[mt][nt][2], acc[mt][nt][3]);
        }
    }
}

extern "C" void kernel_launch(void* const* d_in, const int* in_sizes, int n_in,
                              void* d_out, int out_size) {
    const float* x   = (const float*)d_in[0];
    const float* fs  = (const float*)d_in[1];
    const float* w0  = (const float*)d_in[2];
    const float* w1  = (const float*)d_in[3];
    const float* we0 = (const float*)d_in[4];
    const float* we1 = (const float*)d_in[5];
    float* out = (float*)d_out;

    cudaFuncSetAttribute(k_fwdW_m,   cudaFuncAttributeMaxDynamicSharedMemorySize, FW_SMEM);
    cudaFuncSetAttribute(k_irfftW_m, cudaFuncAttributeMaxDynamicSharedMemorySize, IR_SMEM);

    k_init<<<160, 256>>>();
    k_wtrans<<<4096, 256>>>(w0, w1, we0, we1);
    k_fwdW_m<<<RTOT / 128, 256, FW_SMEM>>>(x);        // 1024 CTAs
    k_fwdH<<<Bsz * CIn * 4, 256>>>();
    k_mix<<<2 * 1024, 256>>>(fs);
    k_invH<<<Bsz * COn * 4, 256>>>();
    k_irfftW_m<<<RTOT / 64, 256, IR_SMEM>>>(out);     // 2048 CTAs
}